// round 13
// baseline (speedup 1.0000x reference)
#include <cuda_runtime.h>
#include <cstdint>

// Problem constants
#define BB   8
#define CIN  64
#define COUT 128
#define HH   224
#define WW   224
#define HW   (HH * WW)
#define PTCH 16
#define GG   14     // 14x14 patch grid
#define NP   196
#define NTILES (BB * GG * GG)   // 1568
#define NBLK2 296               // persistent stage2 blocks (2 per SM)

typedef unsigned long long u64;
typedef unsigned int u32;

// ---------------------------------------------------------------------------
// Scratch (device globals — no allocations allowed)
// ---------------------------------------------------------------------------
__device__ u64 g_pw[NP * 9];                           // packed sign(patch_filters)
__device__ __align__(16) int8_t g_bsa[(size_t)BB * HW * CIN];  // ternary bsa, channels-last

#define WA_STRIDE 592   // 576 + pad; 20 quad-banks mod 32 -> conflict-free LDSM

// ---------------------------------------------------------------------------
// cp.async helpers
// ---------------------------------------------------------------------------
__device__ __forceinline__ void cp16(u32 dst, const void* src, int srcsize) {
    asm volatile("cp.async.cg.shared.global [%0], [%1], 16, %2;\n"
                 :: "r"(dst), "l"(src), "r"(srcsize));
}
__device__ __forceinline__ void cp_commit() { asm volatile("cp.async.commit_group;\n"); }
__device__ __forceinline__ void cp_wait0()  { asm volatile("cp.async.wait_group 0;\n"); }

// ---------------------------------------------------------------------------
// Kernel 0: pack patch-filter sign bits (tiny).
// ---------------------------------------------------------------------------
__global__ void pack_pf_kernel(const float* __restrict__ pf) {
    int i = blockIdx.x * blockDim.x + threadIdx.x;
    if (i >= NP * 9) return;
    int p = i / 9, t = i - p * 9;
    u64 w = 0;
#pragma unroll
    for (int c = 0; c < CIN; c++) {
        unsigned sb = __float_as_uint(pf[((size_t)c * NP + p) * 9 + t]) >> 31;
        w |= (u64)sb << c;
    }
    g_pw[i] = w;
}

// ---------------------------------------------------------------------------
// 32x32 bit-matrix transpose within a warp (5 shfl_xor steps).
// ---------------------------------------------------------------------------
__device__ __forceinline__ u32 bit_transpose32(u32 x, int lane) {
#pragma unroll
    for (int s = 16; s >= 1; s >>= 1) {
        u32 m;
        if      (s == 16) m = 0x0000FFFFu;
        else if (s == 8)  m = 0x00FF00FFu;
        else if (s == 4)  m = 0x0F0F0F0Fu;
        else if (s == 2)  m = 0x33333333u;
        else              m = 0x55555555u;
        u32 y = __shfl_xor_sync(0xFFFFFFFFu, x, s);
        x = (lane & s) ? ((x & ~m) | ((y >> s) & m))
                       : ((x & m) | ((y & m) << s));
    }
    return x;
}

// ---------------------------------------------------------------------------
// Kernel 1: fused sign-pack (ballot + warp bit-transpose) + per-patch
// depthwise binary 3x3 -> ternary int8 bsa.  (validated R10)
// ---------------------------------------------------------------------------
__global__ void __launch_bounds__(256) stage1_kernel(const float* __restrict__ x) {
    __shared__ u64 tile[PTCH][PTCH];
    __shared__ u64 pw9[9];

    const int tid  = threadIdx.x;
    const int w    = tid >> 5, lane = tid & 31;
    const int r    = 2 * w + (lane >> 4);   // patch row for this lane's pixel
    const int col  = lane & 15;             // patch col
    const int gx = blockIdx.x, gy = blockIdx.y, b = blockIdx.z;

    const int y  = gy * PTCH + r;
    const int xc = gx * PTCH + col;
    const float* xp = x + (size_t)b * CIN * HW + (size_t)y * WW + xc;

    u32 halfw[2];
#pragma unroll
    for (int h = 0; h < 2; h++) {
        float v[32];
#pragma unroll
        for (int cc = 0; cc < 32; cc++)
            v[cc] = xp[(size_t)(h * 32 + cc) * HW];
        u32 mym = 0;
#pragma unroll
        for (int cc = 0; cc < 32; cc++) {
            u32 bal = __ballot_sync(0xFFFFFFFFu, __float_as_int(v[cc]) < 0);
            if (lane == cc) mym = bal;
        }
        halfw[h] = bit_transpose32(mym, lane);
    }
    tile[r][col] = (u64)halfw[0] | ((u64)halfw[1] << 32);

    if (tid < 9) pw9[tid] = g_pw[(gy * GG + gx) * 9 + tid];
    __syncthreads();

    const int i = tid >> 4, j = tid & 15;

    u64 c0 = 0, c1 = 0, c2 = 0, c3 = 0;
#pragma unroll
    for (int di = 0; di < 3; di++) {
#pragma unroll
        for (int dj = 0; dj < 3; dj++) {
            int li = i + di - 1, lj = j + dj - 1;
            if (li >= 0 && li < PTCH && lj >= 0 && lj < PTCH) {
                u64 d = tile[li][lj] ^ pw9[di * 3 + dj];
                u64 carry = d, u;
                u = c0 & carry; c0 ^= carry; carry = u;
                u = c1 & carry; c1 ^= carry; carry = u;
                u = c2 & carry; c2 ^= carry; carry = u;
                c3 ^= carry;
            }
        }
    }

    const int ni = (i == 0 || i == PTCH - 1) ? 2 : 3;
    const int nj = (j == 0 || j == PTCH - 1) ? 2 : 3;
    const int n  = ni * nj;

    u64 m, s;
    if (n == 9) {
        m = ~0ULL;
        s = c3 | (c2 & (c1 | c0));
    } else if (n == 6) {
        m = ~(c0 & c1 & ~c2);
        s = c2;
    } else { // n == 4
        m = ~(c1 & ~c0 & ~c2);
        s = (c0 & c1) | c2;
    }

    u32 w32[16];
#pragma unroll
    for (int wi = 0; wi < 16; wi++) {
        u32 v = 0;
#pragma unroll
        for (int bi = 0; bi < 4; bi++) {
            int c = wi * 4 + bi;
            u32 mb = (u32)((m >> c) & 1ULL);
            u32 sb = (u32)((s >> c) & 1ULL);
            u32 byte = mb ? (sb ? 0xFFu : 0x01u) : 0u;
            v |= byte << (bi * 8);
        }
        w32[wi] = v;
    }
    uint4* dst = (uint4*)(g_bsa + ((size_t)((b * HH + gy * PTCH + i) * WW
                                            + gx * PTCH + j)) * CIN);
    dst[0] = make_uint4(w32[0],  w32[1],  w32[2],  w32[3]);
    dst[1] = make_uint4(w32[4],  w32[5],  w32[6],  w32[7]);
    dst[2] = make_uint4(w32[8],  w32[9],  w32[10], w32[11]);
    dst[3] = make_uint4(w32[12], w32[13], w32[14], w32[15]);
}

// ---------------------------------------------------------------------------
// Kernel 2: PERSISTENT split-M(2) int8 implicit GEMM (mma.sync + ldmatrix).
//   Grid = 296 blocks (2/SM) x 256 threads; block owns a fixed 64-channel
//   half (mh). Weights converted float -> +-1 int8 directly into smem in the
//   prologue, overlapped with the first halo cp.async.
//   Per unit: M = 64 (4 m16), N = 256 pixels (32 n8), K = 576.
//   8 N-warps; warp tile 4 m16 x 4 n8; LDSM.x4 fragment loads.
//   (mainloop byte-identical to validated R10 kernel)
// ---------------------------------------------------------------------------
#define HALO_STRIDE 80
#define SMEM_A_BYTES (64 * WA_STRIDE)            // 37888 (half the channels)
#define SMEM_HALO_BYTES (18 * 18 * HALO_STRIDE)  // 25920
#define SMEM_TOTAL (SMEM_A_BYTES + 2 * SMEM_HALO_BYTES)   // 89728

__device__ __forceinline__ void mma_s8(int* d, const u32* a, const u32* b) {
    asm volatile(
        "mma.sync.aligned.m16n8k32.row.col.s32.s8.s8.s32 "
        "{%0,%1,%2,%3}, {%4,%5,%6,%7}, {%8,%9}, {%0,%1,%2,%3};\n"
        : "+r"(d[0]), "+r"(d[1]), "+r"(d[2]), "+r"(d[3])
        : "r"(a[0]), "r"(a[1]), "r"(a[2]), "r"(a[3]),
          "r"(b[0]), "r"(b[1]));
}

__device__ __forceinline__ void ldsm_x4(u32 addr, u32& r0, u32& r1, u32& r2, u32& r3) {
    asm volatile(
        "ldmatrix.sync.aligned.m8n8.x4.shared.b16 {%0,%1,%2,%3}, [%4];"
        : "=r"(r0), "=r"(r1), "=r"(r2), "=r"(r3) : "r"(addr));
}

__device__ __forceinline__ void halo_load(int t, u32 dstbase, int tid) {
    int b = t / NP, r = t - b * NP;
    int ty0 = (r / GG) * 16 - 1, tx0 = (r - (r / GG) * GG) * 16 - 1;
    for (int idx = tid; idx < 324 * 4; idx += 256) {
        int pixel = idx >> 2, c = idx & 3;
        int hy = pixel / 18, hx = pixel - hy * 18;
        int gy = ty0 + hy, gx = tx0 + hx;
        bool ok = (gy >= 0) & (gy < HH) & (gx >= 0) & (gx < WW);
        const int8_t* src = ok
            ? g_bsa + ((size_t)((b * HH + gy) * WW + gx)) * CIN + c * 16
            : g_bsa;
        cp16(dstbase + pixel * HALO_STRIDE + c * 16, src, ok ? 16 : 0);
    }
}

__global__ void __launch_bounds__(256, 2) stage2_kernel(float* __restrict__ out,
                                                        const float* __restrict__ of) {
    extern __shared__ char sm[];
    const u32 smb = (u32)__cvta_generic_to_shared(sm);
    const int tid = threadIdx.x;
    const int mh = blockIdx.x & 1;          // fixed channel half for this block
    const int q  = blockIdx.x >> 1;         // tile start

    // Prologue: first halo via cp.async (overlaps the weight conversion),
    // weights float -> +-1 int8 straight into smem (row o-local, k = t*64+c).
    halo_load(q, smb + SMEM_A_BYTES, tid);
    cp_commit();
    {
        const float* wsrc = of + (size_t)(mh * 64) * CIN * 9;
        for (int e = tid; e < 64 * 576; e += 256) {
            int o = e / 576, kg = e - o * 576;
            int t = kg >> 6, c = kg & 63;
            unsigned sb = __float_as_uint(wsrc[(o * CIN + c) * 9 + t]) >> 31;
            sm[o * WA_STRIDE + kg] = sb ? (int8_t)-1 : (int8_t)1;
        }
    }
    cp_wait0();
    __syncthreads();

    const int warp = tid >> 5, lane = tid & 31;
    const int wn = warp;                    // 8 N-warps
    const int gid = lane >> 2, tig = lane & 3;

    // A LDSM addresses (fixed): 4 m16 tiles over the 64 smem-resident rows.
    u32 aaddr[4];
#pragma unroll
    for (int i = 0; i < 4; i++)
        aaddr[i] = smb + (u32)((i * 16 + (lane & 15)) * WA_STRIDE
                               + ((lane >> 4) << 4));

    // B LDSM lane offsets relative to halo-buffer base.
    u32 brel[2];
    int pty[2];
#pragma unroll
    for (int jr = 0; jr < 2; jr++) {
        int ty = wn * 2 + jr;
        pty[jr] = ty;
        brel[jr] = (u32)((ty * 18 + ((lane >> 4) << 3) + (lane & 7)) * HALO_STRIDE
                         + ((lane >> 3) & 1) * 16);
    }

    int w = 0;
    for (int t = q; t < NTILES; t += 148, w++) {
        const u32 curbase = smb + SMEM_A_BYTES + (u32)((w & 1) * SMEM_HALO_BYTES);

        if (t + 148 < NTILES)
            halo_load(t + 148, smb + SMEM_A_BYTES + (u32)(((w + 1) & 1) * SMEM_HALO_BYTES), tid);
        cp_commit();

        int acc[4][4][4];
#pragma unroll
        for (int i = 0; i < 4; i++)
#pragma unroll
            for (int j = 0; j < 4; j++)
#pragma unroll
                for (int k = 0; k < 4; k++) acc[i][j][k] = 0;

#pragma unroll
        for (int ks = 0; ks < 18; ks++) {
            const int tp = ks >> 1, h = ks & 1;
            const int dy = tp / 3, dx = tp - dy * 3;
            const u32 bofs = (u32)((dy * 18 + dx) * HALO_STRIDE + h * 32);
            const u32 aofs = (u32)(ks * 32);

            u32 a[4][4];
#pragma unroll
            for (int i = 0; i < 4; i++)
                ldsm_x4(aaddr[i] + aofs, a[i][0], a[i][1], a[i][2], a[i][3]);

            u32 bb[2][4];
#pragma unroll
            for (int jr = 0; jr < 2; jr++)
                ldsm_x4(curbase + brel[jr] + bofs, bb[jr][0], bb[jr][1], bb[jr][2], bb[jr][3]);

#pragma unroll
            for (int i = 0; i < 4; i++)
#pragma unroll
                for (int j = 0; j < 4; j++)
                    mma_s8(acc[i][j], a[i], &bb[j >> 1][(j & 1) * 2]);
        }

        // Epilogue
        {
            int b = t / NP, r = t - b * NP;
            int y0 = (r / GG) * 16, x0 = (r - (r / GG) * GG) * 16;
#pragma unroll
            for (int i = 0; i < 4; i++) {
                int o = mh * 64 + i * 16 + gid;
#pragma unroll
                for (int j = 0; j < 4; j++) {
                    int gy = y0 + pty[j >> 1];
                    int gx = x0 + (j & 1) * 8 + tig * 2;
                    size_t base0 = ((size_t)(b * COUT + o)) * HW + (size_t)gy * WW + gx;
                    *(float2*)(out + base0) =
                        make_float2((float)acc[i][j][0], (float)acc[i][j][1]);
                    *(float2*)(out + base0 + (size_t)8 * HW) =
                        make_float2((float)acc[i][j][2], (float)acc[i][j][3]);
                }
            }
        }

        cp_wait0();
        __syncthreads();
    }
}

// ---------------------------------------------------------------------------
// Launch
// ---------------------------------------------------------------------------
extern "C" void kernel_launch(void* const* d_in, const int* in_sizes, int n_in,
                              void* d_out, int out_size) {
    const float* x  = (const float*)d_in[0];
    const float* pf = (const float*)d_in[2];
    const float* of = (const float*)d_in[3];
    float* out = (float*)d_out;

    cudaFuncSetAttribute(stage2_kernel,
                         cudaFuncAttributeMaxDynamicSharedMemorySize, SMEM_TOTAL);

    pack_pf_kernel<<<(NP * 9 + 255) / 256, 256>>>(pf);

    stage1_kernel<<<dim3(GG, GG, BB), 256>>>(x);

    stage2_kernel<<<NBLK2, 256, SMEM_TOTAL>>>(out, of);
}

// round 16
// speedup vs baseline: 1.1429x; 1.1429x over previous
#include <cuda_runtime.h>
#include <cstdint>

// Problem constants
#define BB   8
#define CIN  64
#define COUT 128
#define HH   224
#define WW   224
#define HW   (HH * WW)
#define PTCH 16
#define GG   14     // 14x14 patch grid
#define NP   196
#define NTILES (BB * GG * GG)   // 1568
#define NBLK2 296               // persistent stage2 blocks (2 per SM)

typedef unsigned long long u64;
typedef unsigned int u32;

// ---------------------------------------------------------------------------
// Scratch (device globals — no allocations allowed)
// ---------------------------------------------------------------------------
__device__ __align__(16) int8_t g_bsa[(size_t)BB * HW * CIN];  // ternary bsa, channels-last

#define WA_STRIDE 592   // 576 + pad; 20 quad-banks mod 32 -> conflict-free LDSM
__device__ __align__(16) int8_t g_wA[COUT * WA_STRIDE];  // int8 weights, row o, k = t*64+c

// ---------------------------------------------------------------------------
// cp.async helpers
// ---------------------------------------------------------------------------
__device__ __forceinline__ void cp16(u32 dst, const void* src, int srcsize) {
    asm volatile("cp.async.cg.shared.global [%0], [%1], 16, %2;\n"
                 :: "r"(dst), "l"(src), "r"(srcsize));
}
__device__ __forceinline__ void cp_commit() { asm volatile("cp.async.commit_group;\n"); }
__device__ __forceinline__ void cp_wait0()  { asm volatile("cp.async.wait_group 0;\n"); }

// ---------------------------------------------------------------------------
// 32x32 bit-matrix transpose within a warp (5 shfl_xor steps).
// ---------------------------------------------------------------------------
__device__ __forceinline__ u32 bit_transpose32(u32 x, int lane) {
#pragma unroll
    for (int s = 16; s >= 1; s >>= 1) {
        u32 m;
        if      (s == 16) m = 0x0000FFFFu;
        else if (s == 8)  m = 0x00FF00FFu;
        else if (s == 4)  m = 0x0F0F0F0Fu;
        else if (s == 2)  m = 0x33333333u;
        else              m = 0x55555555u;
        u32 y = __shfl_xor_sync(0xFFFFFFFFu, x, s);
        x = (lane & s) ? ((x & ~m) | ((y >> s) & m))
                       : ((x & m) | ((y & m) << s));
    }
    return x;
}

// ---------------------------------------------------------------------------
// Kernel 1: grid (14, 14, 9).
//   z < 8 : fused sign-pack (ballot + transpose) + per-patch depthwise binary
//           3x3 -> ternary int8 bsa. Patch-filter pack done IN-BLOCK,
//           atomics-free: warps 0/1 ballot the sign bits per tap (lo/hi half).
//   z == 8: pack output-conv weights float -> +-1 int8 into g_wA (196 blocks,
//           co-scheduled with the memory-bound stage1 blocks).
// ---------------------------------------------------------------------------
__global__ void __launch_bounds__(256) stage1_kernel(const float* __restrict__ x,
                                                     const float* __restrict__ pf,
                                                     const float* __restrict__ of) {
    const int tid = threadIdx.x;
    const int gx = blockIdx.x, gy = blockIdx.y, bz = blockIdx.z;

    if (bz == BB) {
        // ---- wA packing blocks (pure writes, no sync) ----
        int idx = (gy * GG + gx) * 256 + tid;
        if (idx < (COUT * WA_STRIDE) / 16) {
            __align__(16) int8_t vals[16];
            int base = idx * 16;
#pragma unroll
            for (int e = 0; e < 16; e++) {
                int pos = base + e;
                int o = pos / WA_STRIDE, kg = pos - o * WA_STRIDE;
                int8_t v = 0;
                if (kg < 576) {
                    int t = kg >> 6, c = kg & 63;
                    unsigned sb = __float_as_uint(of[((size_t)o * CIN + c) * 9 + t]) >> 31;
                    v = sb ? (int8_t)-1 : (int8_t)1;
                }
                vals[e] = v;
            }
            *(uint4*)(g_wA + base) = *(const uint4*)vals;
        }
        return;
    }

    // ---- stage1 blocks ----
    __shared__ u64 tile[PTCH][PTCH];
    __shared__ u32 pwlo[9], pwhi[9];

    const int w    = tid >> 5, lane = tid & 31;
    const int r    = 2 * w + (lane >> 4);   // patch row for this lane's pixel
    const int col  = lane & 15;             // patch col
    const int b    = bz;

    // Patch-filter pack (warps 0,1; atomics-free):
    // lane l of warp w owns channel w*32 + l; its 9 pf taps are contiguous.
    // Per tap: ballot gives the 32-channel sign half-word; lane t stores tap t.
    if (w < 2) {
        const int p = gy * GG + gx;
        const int c = w * 32 + lane;
        const float* pfp = pf + ((size_t)c * NP + p) * 9;
        float f[9];
#pragma unroll
        for (int t = 0; t < 9; t++) f[t] = pfp[t];
#pragma unroll
        for (int t = 0; t < 9; t++) {
            u32 bal = __ballot_sync(0xFFFFFFFFu, __float_as_int(f[t]) < 0);
            if (lane == t) {
                if (w == 0) pwlo[t] = bal; else pwhi[t] = bal;
            }
        }
    }

    // Input sign-pack: ballot per channel + warp bit-transpose.
    const int y  = gy * PTCH + r;
    const int xc = gx * PTCH + col;
    const float* xp = x + (size_t)b * CIN * HW + (size_t)y * WW + xc;

    u32 halfw[2];
#pragma unroll
    for (int h = 0; h < 2; h++) {
        float v[32];
#pragma unroll
        for (int cc = 0; cc < 32; cc++)
            v[cc] = xp[(size_t)(h * 32 + cc) * HW];
        u32 mym = 0;
#pragma unroll
        for (int cc = 0; cc < 32; cc++) {
            u32 bal = __ballot_sync(0xFFFFFFFFu, __float_as_int(v[cc]) < 0);
            if (lane == cc) mym = bal;
        }
        halfw[h] = bit_transpose32(mym, lane);
    }
    tile[r][col] = (u64)halfw[0] | ((u64)halfw[1] << 32);

    __syncthreads();   // tile + pwlo/pwhi visible

    const int i = tid >> 4, j = tid & 15;

    u64 c0 = 0, c1 = 0, c2 = 0, c3 = 0;
#pragma unroll
    for (int di = 0; di < 3; di++) {
#pragma unroll
        for (int dj = 0; dj < 3; dj++) {
            int li = i + di - 1, lj = j + dj - 1;
            if (li >= 0 && li < PTCH && lj >= 0 && lj < PTCH) {
                int tp = di * 3 + dj;
                u64 pw = (u64)pwlo[tp] | ((u64)pwhi[tp] << 32);
                u64 d = tile[li][lj] ^ pw;
                u64 carry = d, u;
                u = c0 & carry; c0 ^= carry; carry = u;
                u = c1 & carry; c1 ^= carry; carry = u;
                u = c2 & carry; c2 ^= carry; carry = u;
                c3 ^= carry;
            }
        }
    }

    const int ni = (i == 0 || i == PTCH - 1) ? 2 : 3;
    const int nj = (j == 0 || j == PTCH - 1) ? 2 : 3;
    const int n  = ni * nj;

    u64 m, s;
    if (n == 9) {
        m = ~0ULL;
        s = c3 | (c2 & (c1 | c0));
    } else if (n == 6) {
        m = ~(c0 & c1 & ~c2);
        s = c2;
    } else { // n == 4
        m = ~(c1 & ~c0 & ~c2);
        s = (c0 & c1) | c2;
    }

    u32 w32[16];
#pragma unroll
    for (int wi = 0; wi < 16; wi++) {
        u32 v = 0;
#pragma unroll
        for (int bi = 0; bi < 4; bi++) {
            int c = wi * 4 + bi;
            u32 mb = (u32)((m >> c) & 1ULL);
            u32 sb = (u32)((s >> c) & 1ULL);
            u32 byte = mb ? (sb ? 0xFFu : 0x01u) : 0u;
            v |= byte << (bi * 8);
        }
        w32[wi] = v;
    }
    uint4* dst = (uint4*)(g_bsa + ((size_t)((b * HH + gy * PTCH + i) * WW
                                            + gx * PTCH + j)) * CIN);
    dst[0] = make_uint4(w32[0],  w32[1],  w32[2],  w32[3]);
    dst[1] = make_uint4(w32[4],  w32[5],  w32[6],  w32[7]);
    dst[2] = make_uint4(w32[8],  w32[9],  w32[10], w32[11]);
    dst[3] = make_uint4(w32[12], w32[13], w32[14], w32[15]);
}

// ---------------------------------------------------------------------------
// Kernel 2: PERSISTENT split-M(2) int8 implicit GEMM (mma.sync + ldmatrix).
// Byte-identical to validated R10 kernel (127.4 us total, stage2 92.5 us).
// ---------------------------------------------------------------------------
#define HALO_STRIDE 80
#define SMEM_A_BYTES (64 * WA_STRIDE)            // 37888 (half the channels)
#define SMEM_HALO_BYTES (18 * 18 * HALO_STRIDE)  // 25920
#define SMEM_TOTAL (SMEM_A_BYTES + 2 * SMEM_HALO_BYTES)   // 89728

__device__ __forceinline__ void mma_s8(int* d, const u32* a, const u32* b) {
    asm volatile(
        "mma.sync.aligned.m16n8k32.row.col.s32.s8.s8.s32 "
        "{%0,%1,%2,%3}, {%4,%5,%6,%7}, {%8,%9}, {%0,%1,%2,%3};\n"
        : "+r"(d[0]), "+r"(d[1]), "+r"(d[2]), "+r"(d[3])
        : "r"(a[0]), "r"(a[1]), "r"(a[2]), "r"(a[3]),
          "r"(b[0]), "r"(b[1]));
}

__device__ __forceinline__ void ldsm_x4(u32 addr, u32& r0, u32& r1, u32& r2, u32& r3) {
    asm volatile(
        "ldmatrix.sync.aligned.m8n8.x4.shared.b16 {%0,%1,%2,%3}, [%4];"
        : "=r"(r0), "=r"(r1), "=r"(r2), "=r"(r3) : "r"(addr));
}

__device__ __forceinline__ void halo_load(int t, u32 dstbase, int tid) {
    int b = t / NP, r = t - b * NP;
    int ty0 = (r / GG) * 16 - 1, tx0 = (r - (r / GG) * GG) * 16 - 1;
    for (int idx = tid; idx < 324 * 4; idx += 256) {
        int pixel = idx >> 2, c = idx & 3;
        int hy = pixel / 18, hx = pixel - hy * 18;
        int gy = ty0 + hy, gx = tx0 + hx;
        bool ok = (gy >= 0) & (gy < HH) & (gx >= 0) & (gx < WW);
        const int8_t* src = ok
            ? g_bsa + ((size_t)((b * HH + gy) * WW + gx)) * CIN + c * 16
            : g_bsa;
        cp16(dstbase + pixel * HALO_STRIDE + c * 16, src, ok ? 16 : 0);
    }
}

__global__ void __launch_bounds__(256, 2) stage2_kernel(float* __restrict__ out) {
    extern __shared__ char sm[];
    const u32 smb = (u32)__cvta_generic_to_shared(sm);
    const int tid = threadIdx.x;
    const int mh = blockIdx.x & 1;          // fixed channel half for this block
    const int q  = blockIdx.x >> 1;         // tile start

    {
        const int8_t* wsrc = g_wA + (size_t)(mh * 64) * WA_STRIDE;
        for (int i = tid; i < SMEM_A_BYTES / 16; i += 256)
            cp16(smb + i * 16, wsrc + i * 16, 16);
    }
    halo_load(q, smb + SMEM_A_BYTES, tid);
    cp_commit();
    cp_wait0();
    __syncthreads();

    const int warp = tid >> 5, lane = tid & 31;
    const int wn = warp;                    // 8 N-warps
    const int gid = lane >> 2, tig = lane & 3;

    u32 aaddr[4];
#pragma unroll
    for (int i = 0; i < 4; i++)
        aaddr[i] = smb + (u32)((i * 16 + (lane & 15)) * WA_STRIDE
                               + ((lane >> 4) << 4));

    u32 brel[2];
    int pty[2];
#pragma unroll
    for (int jr = 0; jr < 2; jr++) {
        int ty = wn * 2 + jr;
        pty[jr] = ty;
        brel[jr] = (u32)((ty * 18 + ((lane >> 4) << 3) + (lane & 7)) * HALO_STRIDE
                         + ((lane >> 3) & 1) * 16);
    }

    int w = 0;
    for (int t = q; t < NTILES; t += 148, w++) {
        const u32 curbase = smb + SMEM_A_BYTES + (u32)((w & 1) * SMEM_HALO_BYTES);

        if (t + 148 < NTILES)
            halo_load(t + 148, smb + SMEM_A_BYTES + (u32)(((w + 1) & 1) * SMEM_HALO_BYTES), tid);
        cp_commit();

        int acc[4][4][4];
#pragma unroll
        for (int i = 0; i < 4; i++)
#pragma unroll
            for (int j = 0; j < 4; j++)
#pragma unroll
                for (int k = 0; k < 4; k++) acc[i][j][k] = 0;

#pragma unroll
        for (int ks = 0; ks < 18; ks++) {
            const int tp = ks >> 1, h = ks & 1;
            const int dy = tp / 3, dx = tp - dy * 3;
            const u32 bofs = (u32)((dy * 18 + dx) * HALO_STRIDE + h * 32);
            const u32 aofs = (u32)(ks * 32);

            u32 a[4][4];
#pragma unroll
            for (int i = 0; i < 4; i++)
                ldsm_x4(aaddr[i] + aofs, a[i][0], a[i][1], a[i][2], a[i][3]);

            u32 bb[2][4];
#pragma unroll
            for (int jr = 0; jr < 2; jr++)
                ldsm_x4(curbase + brel[jr] + bofs, bb[jr][0], bb[jr][1], bb[jr][2], bb[jr][3]);

#pragma unroll
            for (int i = 0; i < 4; i++)
#pragma unroll
                for (int j = 0; j < 4; j++)
                    mma_s8(acc[i][j], a[i], &bb[j >> 1][(j & 1) * 2]);
        }

        {
            int b = t / NP, r = t - b * NP;
            int y0 = (r / GG) * 16, x0 = (r - (r / GG) * GG) * 16;
#pragma unroll
            for (int i = 0; i < 4; i++) {
                int o = mh * 64 + i * 16 + gid;
#pragma unroll
                for (int j = 0; j < 4; j++) {
                    int gy = y0 + pty[j >> 1];
                    int gx = x0 + (j & 1) * 8 + tig * 2;
                    size_t base0 = ((size_t)(b * COUT + o)) * HW + (size_t)gy * WW + gx;
                    *(float2*)(out + base0) =
                        make_float2((float)acc[i][j][0], (float)acc[i][j][1]);
                    *(float2*)(out + base0 + (size_t)8 * HW) =
                        make_float2((float)acc[i][j][2], (float)acc[i][j][3]);
                }
            }
        }

        cp_wait0();
        __syncthreads();
    }
}

// ---------------------------------------------------------------------------
// Launch: two kernels total.
// ---------------------------------------------------------------------------
extern "C" void kernel_launch(void* const* d_in, const int* in_sizes, int n_in,
                              void* d_out, int out_size) {
    const float* x  = (const float*)d_in[0];
    const float* pf = (const float*)d_in[2];
    const float* of = (const float*)d_in[3];
    float* out = (float*)d_out;

    cudaFuncSetAttribute(stage2_kernel,
                         cudaFuncAttributeMaxDynamicSharedMemorySize, SMEM_TOTAL);

    stage1_kernel<<<dim3(GG, GG, BB + 1), 256>>>(x, pf, of);

    stage2_kernel<<<NBLK2, 256, SMEM_TOTAL>>>(out);
}